// round 14
// baseline (speedup 1.0000x reference)
#include <cuda_runtime.h>
#include <cuda_fp16.h>
#include <math.h>
#include <stdint.h>

#define SEQ   2048
#define HID   2048
#define HD    128
#define NH    16

// Scratch (device globals: allocation-free rule)
__device__ __half g_Qh[SEQ * HID];
__device__ __half g_Kh[SEQ * HID];
__device__ __half g_Vh[SEQ * HID];
__device__ __half g_Oh[SEQ * HID];
__device__ __half g_Xh[SEQ * HID];
__device__ __half g_W0h[HID * HID];
__device__ __half g_W1h[HID * HID];
__device__ __half g_W2h[HID * HID];
__device__ __half g_W3h[HID * HID];

// attn+out queue: [0]=counter, [1..256] attention done flags (qb*16+h)
#define AO_ATTN 256
#define AO_OUT  256
#define AO_ITEMS (AO_ATTN + AO_OUT)
__device__ int g_queue[1 + AO_ATTN];

// ===========================================================================
// Helpers
// ===========================================================================
__device__ __forceinline__ uint32_t smem_u32(const void* p) {
    uint32_t a;
    asm("{ .reg .u64 t; cvta.to.shared.u64 t, %1; cvt.u32.u64 %0, t; }"
        : "=r"(a) : "l"(p));
    return a;
}
__device__ __forceinline__ void cp_async16(uint32_t dst, const void* src) {
    asm volatile("cp.async.cg.shared.global [%0], [%1], 16;" :: "r"(dst), "l"(src));
}
#define CP_COMMIT() asm volatile("cp.async.commit_group;" ::: "memory")
#define CP_WAIT(n)  asm volatile("cp.async.wait_group %0;" :: "n"(n) : "memory")

__device__ __forceinline__ uint32_t pack_h2(float lo, float hi) {
    __half2 h = __floats2half2_rn(lo, hi);
    return *(uint32_t*)&h;
}
__device__ __forceinline__ int ld_acquire(const int* p) {
    int v;
    asm volatile("ld.acquire.gpu.global.b32 %0, [%1];" : "=r"(v) : "l"(p));
    return v;
}
__device__ __forceinline__ void st_release(int* p, int v) {
    asm volatile("st.release.gpu.global.b32 [%0], %1;" :: "l"(p), "r"(v));
}

__device__ __forceinline__ void ldsm_x4(uint32_t r[4], uint32_t addr) {
    asm volatile("ldmatrix.sync.aligned.m8n8.x4.shared.b16 {%0,%1,%2,%3}, [%4];"
        : "=r"(r[0]), "=r"(r[1]), "=r"(r[2]), "=r"(r[3]) : "r"(addr));
}
__device__ __forceinline__ void ldsm_x4_t(uint32_t r[4], uint32_t addr) {
    asm volatile("ldmatrix.sync.aligned.m8n8.x4.trans.shared.b16 {%0,%1,%2,%3}, [%4];"
        : "=r"(r[0]), "=r"(r[1]), "=r"(r[2]), "=r"(r[3]) : "r"(addr));
}

__device__ __forceinline__ void mma_f16(float c[4], const uint32_t a[4],
                                        const uint32_t b[2]) {
    asm volatile(
        "mma.sync.aligned.m16n8k16.row.col.f32.f16.f16.f32 "
        "{%0,%1,%2,%3}, {%4,%5,%6,%7}, {%8,%9}, {%0,%1,%2,%3};"
        : "+f"(c[0]), "+f"(c[1]), "+f"(c[2]), "+f"(c[3])
        : "r"(a[0]), "r"(a[1]), "r"(a[2]), "r"(a[3]), "r"(b[0]), "r"(b[1]));
}

// ===========================================================================
// Fused fp32 -> fp16 conversion prepass (5 tensors, 2 float4/thread)
// ===========================================================================
__global__ __launch_bounds__(256) void cvt_f16_5(
    const float4* __restrict__ i0, const float4* __restrict__ i1,
    const float4* __restrict__ i2, const float4* __restrict__ i3,
    const float4* __restrict__ i4,
    __half* __restrict__ o0, __half* __restrict__ o1,
    __half* __restrict__ o2, __half* __restrict__ o3,
    __half* __restrict__ o4, int n4)
{
    const int z = blockIdx.y;
    const float4* in = (z == 0) ? i0 : (z == 1) ? i1 : (z == 2) ? i2
                      : (z == 3) ? i3 : i4;
    __half* out      = (z == 0) ? o0 : (z == 1) ? o1 : (z == 2) ? o2
                      : (z == 3) ? o3 : o4;
    int i = 2 * (blockIdx.x * blockDim.x + threadIdx.x);
    if (i + 1 >= n4) {
        if (i < n4) {
            float4 v = in[i];
            uint2 h;
            h.x = pack_h2(v.x, v.y);
            h.y = pack_h2(v.z, v.w);
            ((uint2*)out)[i] = h;
        }
        return;
    }
    float4 va = in[i];
    float4 vb = in[i + 1];
    uint2 ha, hb;
    ha.x = pack_h2(va.x, va.y); ha.y = pack_h2(va.z, va.w);
    hb.x = pack_h2(vb.x, vb.y); hb.y = pack_h2(vb.z, vb.w);
    ((uint2*)out)[i]     = ha;
    ((uint2*)out)[i + 1] = hb;
}

// ===========================================================================
// fp16 mma.sync GEMM core, templated on B-tile rows (BNT = 256 or 128).
// CTA tile 128 x BNT, 8 warps of 64 x (BNT/4), BK=64, 3-stage cp.async.
// ===========================================================================
#define BM 128
#define BK 64
#define NST 3
#define ROWPH 72
#define ATFH (BM * ROWPH)
#define GEMM_SMEM_BYTES (NST * ((BM + 256) * ROWPH) * 2)    // 165888 (max)

template <int BNT>
__device__ __forceinline__ void gemm_load_stage(
    const __half* __restrict__ Ab, const __half* __restrict__ Bb,
    __half* sm, int slot, int k0, int tid)
{
    constexpr int RTOT = BM + BNT;
    constexpr int STF_ = RTOT * ROWPH;
    const uint32_t sbase = smem_u32(sm) + (uint32_t)(slot * STF_) * 2u;
#pragma unroll
    for (int it = 0; it < RTOT / 32; it++) {
        const int idx = tid + it * 256;
        const int r = idx >> 3;
        const int q = idx & 7;
        const __half* src = (r < BM) ? (Ab + (size_t)r * HID + k0 + q * 8)
                                     : (Bb + (size_t)(r - BM) * HID + k0 + q * 8);
        cp_async16(sbase + (uint32_t)(r * ROWPH + q * 8) * 2u, src);
    }
}

template <bool HALF_OUT, int BNT>
__device__ __forceinline__ void gemm_body(
    const __half* __restrict__ A, const __half* __restrict__ B,
    const float* __restrict__ bias, void* __restrict__ Cv,
    __half* sm, int row0, int col0)
{
    constexpr int NTC  = BNT / 32;    // n-subtiles per warp (8 or 4)
    constexpr int WNT  = BNT / 4;     // warp n width (64 or 32)
    constexpr int STF_ = (BM + BNT) * ROWPH;

    const int tid  = threadIdx.x;
    const int wid  = tid >> 5;
    const int lane = tid & 31;
    const int lr   = lane >> 2;
    const int lc   = lane & 3;
    const int l15  = lane & 15;
    const int klo  = (lane >> 4) << 3;
    const int wm   = (wid >> 2) * 64;
    const int wn   = (wid & 3) * WNT;

    const __half* Ab = A + (size_t)row0 * HID;
    const __half* Bb = B + (size_t)col0 * HID;

    float acc[4][NTC][4];
#pragma unroll
    for (int mt = 0; mt < 4; mt++)
#pragma unroll
        for (int nt = 0; nt < NTC; nt++)
#pragma unroll
            for (int i = 0; i < 4; i++) acc[mt][nt][i] = 0.0f;

#pragma unroll
    for (int s = 0; s < NST - 1; s++) {
        gemm_load_stage<BNT>(Ab, Bb, sm, s, s * BK, tid);
        CP_COMMIT();
    }

    const uint32_t sbase = smem_u32(sm);
    const int KCH = HID / BK;   // 32
    for (int j = 0; j < KCH; j++) {
        CP_WAIT(NST - 2);
        __syncthreads();
        if (j + NST - 1 < KCH) {
            gemm_load_stage<BNT>(Ab, Bb, sm, (j + NST - 1) % NST, (j + NST - 1) * BK, tid);
        }
        CP_COMMIT();

        const uint32_t sa = sbase + (uint32_t)((j % NST) * STF_) * 2u;
        const uint32_t sb = sa + (uint32_t)ATFH * 2u;

#pragma unroll
        for (int kk = 0; kk < BK; kk += 16) {
            uint32_t af[4][4], bf[NTC][2];
#pragma unroll
            for (int mt = 0; mt < 4; mt++)
                ldsm_x4(af[mt],
                        sa + (uint32_t)((wm + mt * 16 + l15) * ROWPH + kk + klo) * 2u);
#pragma unroll
            for (int np = 0; np < NTC / 2; np++) {
                uint32_t t[4];
                ldsm_x4(t,
                        sb + (uint32_t)((wn + np * 16 + l15) * ROWPH + kk + klo) * 2u);
                bf[2 * np + 0][0] = t[0];
                bf[2 * np + 1][0] = t[1];
                bf[2 * np + 0][1] = t[2];
                bf[2 * np + 1][1] = t[3];
            }
#pragma unroll
            for (int mt = 0; mt < 4; mt++)
#pragma unroll
                for (int nt = 0; nt < NTC; nt++)
                    mma_f16(acc[mt][nt], af[mt], bf[nt]);
        }
    }

#pragma unroll
    for (int mt = 0; mt < 4; mt++) {
#pragma unroll
        for (int half = 0; half < 2; half++) {
            const int r = row0 + wm + mt * 16 + lr + half * 8;
#pragma unroll
            for (int nt = 0; nt < NTC; nt++) {
                const int c = col0 + wn + nt * 8 + 2 * lc;
                const float vx = acc[mt][nt][half * 2 + 0] + bias[c];
                const float vy = acc[mt][nt][half * 2 + 1] + bias[c + 1];
                if (HALF_OUT) {
                    __half* crow = (__half*)Cv + (size_t)r * HID;
                    *(uint32_t*)(crow + c) = pack_h2(vx, vy);
                } else {
                    float* crow = (float*)Cv + (size_t)r * HID;
                    *(float2*)(crow + c) = make_float2(vx, vy);
                }
            }
        }
    }
}

// Fused QKV projection (grid launch, R10-proven): blockIdx.z selects W/bias/C.
__global__ __launch_bounds__(256, 1) void gemm_qkv(
    const __half* __restrict__ A,
    const __half* __restrict__ W0, const __half* __restrict__ W1,
    const __half* __restrict__ W2,
    const float* __restrict__ b0, const float* __restrict__ b1,
    const float* __restrict__ b2,
    __half* __restrict__ C0, __half* __restrict__ C1, __half* __restrict__ C2)
{
    extern __shared__ __half smh[];
    const int z = blockIdx.z;
    const __half* B   = (z == 0) ? W0 : (z == 1) ? W1 : W2;
    const float* bias = (z == 0) ? b0 : (z == 1) ? b1 : b2;
    __half* C         = (z == 0) ? C0 : (z == 1) ? C1 : C2;
    gemm_body<true, 256>(A, B, bias, C, smh, blockIdx.y * BM, blockIdx.x * 256);
}

// ===========================================================================
// Flash attention body (fp16 m16n8k16), 3-slot KV ring, one tile = 128q x 1 head
// ===========================================================================
#define FSK 64
#define FSTG 3
#define KPH 136
#define KTILEH (FSK * KPH)
#define FSTAGEH (2 * KTILEH)

__device__ __forceinline__ void flash_load_kv(
    const __half* __restrict__ K, const __half* __restrict__ V,
    __half* sm, int slot, int kt, int hcol, int tid)
{
    const uint32_t ka = smem_u32(sm) + (uint32_t)(slot * FSTAGEH) * 2u;
    const uint32_t va = ka + (uint32_t)KTILEH * 2u;
    const int base = kt * FSK;
#pragma unroll
    for (int it = 0; it < 4; it++) {
        const int idx = tid + it * 256;
        const int r = idx >> 4;
        const int q = idx & 15;
        cp_async16(ka + (uint32_t)(r * KPH + q * 8) * 2u,
                   K + (size_t)(base + r) * HID + hcol + q * 8);
        cp_async16(va + (uint32_t)(r * KPH + q * 8) * 2u,
                   V + (size_t)(base + r) * HID + hcol + q * 8);
    }
}

__device__ __forceinline__ void attn_body(
    const __half* __restrict__ Q, const __half* __restrict__ K,
    const __half* __restrict__ V, __half* __restrict__ O,
    const float* __restrict__ order_gate, const float* __restrict__ justice_gate,
    __half* fsmh, int h, int qb)
{
    const int tid  = threadIdx.x;
    const int wid  = tid >> 5;
    const int lane = tid & 31;
    const int lr   = lane >> 2;
    const int lc   = lane & 3;
    const int l15  = lane & 15;
    const int klo  = (lane >> 4) << 3;
    const int hcol = h * HD;
    const int qbase = qb * 128 + wid * 16;

    const float sig_j = 1.0f / (1.0f + __expf(-justice_gate[0]));
    const float sig_o = 1.0f / (1.0f + __expf(-order_gate[0]));
    const float alpha = (1.0f - 0.1f * sig_j) * rsqrtf((float)HD);
    const float obias = sig_o * 0.05f / (float)SEQ;

    uint32_t qf[8][4];
    {
        const __half* Qb = Q + (size_t)qbase * HID + hcol;
#pragma unroll
        for (int ks = 0; ks < 8; ks++) {
            qf[ks][0] = *(const uint32_t*)(Qb + (size_t)lr * HID + ks * 16 + 2 * lc);
            qf[ks][1] = *(const uint32_t*)(Qb + (size_t)(lr + 8) * HID + ks * 16 + 2 * lc);
            qf[ks][2] = *(const uint32_t*)(Qb + (size_t)lr * HID + ks * 16 + 2 * lc + 8);
            qf[ks][3] = *(const uint32_t*)(Qb + (size_t)(lr + 8) * HID + ks * 16 + 2 * lc + 8);
        }
    }

    float m0 = -1.0e30f, m1 = -1.0e30f, l0 = 0.0f, l1 = 0.0f;
    float of[16][4];
#pragma unroll
    for (int nt = 0; nt < 16; nt++)
#pragma unroll
        for (int i = 0; i < 4; i++) of[nt][i] = 0.0f;

    flash_load_kv(K, V, fsmh, 0, 0, hcol, tid);
    CP_COMMIT();
    flash_load_kv(K, V, fsmh, 1, 1, hcol, tid);
    CP_COMMIT();

    const int NT = SEQ / FSK;   // 32
    for (int kt = 0; kt < NT; kt++) {
        CP_WAIT(1);
        __syncthreads();
        if (kt + 2 < NT) {
            flash_load_kv(K, V, fsmh, (kt + 2) % FSTG, kt + 2, hcol, tid);
        }
        CP_COMMIT();

        const uint32_t ksa = smem_u32(fsmh) + (uint32_t)((kt % FSTG) * FSTAGEH) * 2u;
        const uint32_t vsa = ksa + (uint32_t)KTILEH * 2u;

        float sf[8][4];
#pragma unroll
        for (int nt = 0; nt < 8; nt++)
#pragma unroll
            for (int i = 0; i < 4; i++) sf[nt][i] = 0.0f;

#pragma unroll
        for (int ks = 0; ks < 8; ks++) {
            uint32_t bf[8][2];
#pragma unroll
            for (int np = 0; np < 4; np++) {
                uint32_t t[4];
                ldsm_x4(t, ksa + (uint32_t)((np * 16 + l15) * KPH + ks * 16 + klo) * 2u);
                bf[2 * np + 0][0] = t[0];
                bf[2 * np + 1][0] = t[1];
                bf[2 * np + 0][1] = t[2];
                bf[2 * np + 1][1] = t[3];
            }
#pragma unroll
            for (int nt = 0; nt < 8; nt++)
                mma_f16(sf[nt], qf[ks], bf[nt]);
        }

        float rmax0 = -1.0e30f, rmax1 = -1.0e30f;
#pragma unroll
        for (int nt = 0; nt < 8; nt++) {
            const float col0 = (float)(kt * FSK + nt * 8 + 2 * lc);
            sf[nt][0] = fmaf(sf[nt][0], alpha, obias * col0);
            sf[nt][1] = fmaf(sf[nt][1], alpha, obias * (col0 + 1.0f));
            sf[nt][2] = fmaf(sf[nt][2], alpha, obias * col0);
            sf[nt][3] = fmaf(sf[nt][3], alpha, obias * (col0 + 1.0f));
            rmax0 = fmaxf(rmax0, fmaxf(sf[nt][0], sf[nt][1]));
            rmax1 = fmaxf(rmax1, fmaxf(sf[nt][2], sf[nt][3]));
        }
#pragma unroll
        for (int off = 1; off < 4; off <<= 1) {
            rmax0 = fmaxf(rmax0, __shfl_xor_sync(0xffffffffu, rmax0, off));
            rmax1 = fmaxf(rmax1, __shfl_xor_sync(0xffffffffu, rmax1, off));
        }
        const float m0n = fmaxf(m0, rmax0);
        const float m1n = fmaxf(m1, rmax1);
        const float corr0 = __expf(m0 - m0n);
        const float corr1 = __expf(m1 - m1n);

        float rsum0 = 0.0f, rsum1 = 0.0f;
        uint32_t ph[8][2];
#pragma unroll
        for (int nt = 0; nt < 8; nt++) {
            const float e0 = __expf(sf[nt][0] - m0n);
            const float e1 = __expf(sf[nt][1] - m0n);
            const float e2 = __expf(sf[nt][2] - m1n);
            const float e3 = __expf(sf[nt][3] - m1n);
            rsum0 += e0 + e1;
            rsum1 += e2 + e3;
            ph[nt][0] = pack_h2(e0, e1);
            ph[nt][1] = pack_h2(e2, e3);
        }
#pragma unroll
        for (int off = 1; off < 4; off <<= 1) {
            rsum0 += __shfl_xor_sync(0xffffffffu, rsum0, off);
            rsum1 += __shfl_xor_sync(0xffffffffu, rsum1, off);
        }
        l0 = l0 * corr0 + rsum0; m0 = m0n;
        l1 = l1 * corr1 + rsum1; m1 = m1n;

#pragma unroll
        for (int nt = 0; nt < 16; nt++) {
            of[nt][0] *= corr0; of[nt][1] *= corr0;
            of[nt][2] *= corr1; of[nt][3] *= corr1;
        }

#pragma unroll
        for (int kp = 0; kp < 4; kp++) {
            uint32_t pa[4];
            pa[0] = ph[2 * kp + 0][0];
            pa[1] = ph[2 * kp + 0][1];
            pa[2] = ph[2 * kp + 1][0];
            pa[3] = ph[2 * kp + 1][1];
#pragma unroll
            for (int dg = 0; dg < 8; dg++) {
                uint32_t t[4];
                ldsm_x4_t(t, vsa + (uint32_t)((kp * 16 + l15) * KPH + dg * 16 + klo) * 2u);
                uint32_t b0[2] = {t[0], t[1]};
                uint32_t b1[2] = {t[2], t[3]};
                mma_f16(of[2 * dg + 0], pa, b0);
                mma_f16(of[2 * dg + 1], pa, b1);
            }
        }
    }

    const float invl0 = 1.0f / l0;
    const float invl1 = 1.0f / l1;
    __half* Ob = O + (size_t)qbase * HID + hcol;
#pragma unroll
    for (int nt = 0; nt < 16; nt++) {
        const int c = nt * 8 + 2 * lc;
        *(uint32_t*)(Ob + (size_t)lr * HID + c) =
            pack_h2(of[nt][0] * invl0, of[nt][1] * invl0);
        *(uint32_t*)(Ob + (size_t)(lr + 8) * HID + c) =
            pack_h2(of[nt][2] * invl1, of[nt][3] * invl1);
    }
}

// ===========================================================================
// Persistent attn + output-projection kernel.
// Queue: 256 attention tiles (qb-major: item = qb*16 + h, dep-free), then
// 256 output tiles 128x128 (y-major: o = item-256, y = o>>4, x = o&15),
// each waiting on the 16 attention flags of its row block.
// Small output tiles backfill the attention tail (work-conserving).
// ===========================================================================
__global__ __launch_bounds__(256, 1) void attn_out_fused(
    const __half* __restrict__ Q, const __half* __restrict__ K,
    const __half* __restrict__ V, __half* __restrict__ O,
    const __half* __restrict__ W3, const float* __restrict__ b3,
    float* __restrict__ out,
    const float* __restrict__ order_gate, const float* __restrict__ justice_gate,
    int* __restrict__ queue)
{
    extern __shared__ __half smh[];
    __shared__ int s_item;

    for (;;) {
        __syncthreads();
        if (threadIdx.x == 0) s_item = atomicAdd(&queue[0], 1);
        __syncthreads();
        const int item = s_item;
        if (item >= AO_ITEMS) return;

        if (item < AO_ATTN) {
            const int qb = item >> 4;
            const int h  = item & 15;
            attn_body(Q, K, V, O, order_gate, justice_gate, smh, h, qb);
            __threadfence();
            __syncthreads();
            if (threadIdx.x == 0) st_release(&queue[1 + item], 1);
        } else {
            const int o = item - AO_ATTN;
            const int y = o >> 4;              // row block 0..15
            const int x = o & 15;              // col block 0..15 (128 cols each)
            if (threadIdx.x < 16) {
                while (ld_acquire(&queue[1 + y * 16 + threadIdx.x]) == 0)
                    __nanosleep(200);
            }
            __syncthreads();
            gemm_body<false, 128>(O, W3, b3, out, smh, y * BM, x * 128);
        }
    }
}

// ===========================================================================
extern "C" void kernel_launch(void* const* d_in, const int* in_sizes, int n_in,
                              void* d_out, int out_size)
{
    const float* X  = (const float*)d_in[0];
    const float* Wq = (const float*)d_in[1];
    const float* bq = (const float*)d_in[2];
    const float* Wk = (const float*)d_in[3];
    const float* bk = (const float*)d_in[4];
    const float* Wv = (const float*)d_in[5];
    const float* bv = (const float*)d_in[6];
    const float* Wo = (const float*)d_in[7];
    const float* bo = (const float*)d_in[8];
    const float* order_gate   = (const float*)d_in[11];
    const float* justice_gate = (const float*)d_in[12];
    float* out = (float*)d_out;

    __half *qp, *kp, *vp, *op, *xh, *w0, *w1, *w2, *w3;
    int* qptr;
    cudaGetSymbolAddress((void**)&qp, g_Qh);
    cudaGetSymbolAddress((void**)&kp, g_Kh);
    cudaGetSymbolAddress((void**)&vp, g_Vh);
    cudaGetSymbolAddress((void**)&op, g_Oh);
    cudaGetSymbolAddress((void**)&xh, g_Xh);
    cudaGetSymbolAddress((void**)&w0, g_W0h);
    cudaGetSymbolAddress((void**)&w1, g_W1h);
    cudaGetSymbolAddress((void**)&w2, g_W2h);
    cudaGetSymbolAddress((void**)&w3, g_W3h);
    cudaGetSymbolAddress((void**)&qptr, g_queue);

    cudaFuncSetAttribute(gemm_qkv,
                         cudaFuncAttributeMaxDynamicSharedMemorySize,
                         GEMM_SMEM_BYTES);
    cudaFuncSetAttribute(attn_out_fused,
                         cudaFuncAttributeMaxDynamicSharedMemorySize,
                         GEMM_SMEM_BYTES);

    int dev = 0, nsm = 148;
    cudaGetDevice(&dev);
    cudaDeviceGetAttribute(&nsm, cudaDevAttrMultiProcessorCount, dev);
    if (nsm <= 0 || nsm > AO_ITEMS) nsm = 148;

    const int N4 = (HID * HID) / 4;

    // reset queue + attention flags (graph-capturable async memset)
    cudaMemsetAsync(qptr, 0, sizeof(int) * (1 + AO_ATTN));

    // prepass: convert all 5 fp32 inputs to fp16
    dim3 rg((N4 / 2 + 255) / 256, 5);
    cvt_f16_5<<<rg, 256>>>((const float4*)X,  (const float4*)Wq,
                           (const float4*)Wk, (const float4*)Wv,
                           (const float4*)Wo,
                           xh, w0, w1, w2, w3, N4);

    // QKV projections (grid launch, one kernel, z = 0/1/2)
    dim3 gq(HID / 256, SEQ / BM, 3);   // 8 x 16 x 3
    gemm_qkv<<<gq, 256, GEMM_SMEM_BYTES>>>(xh, w0, w1, w2, bq, bk, bv,
                                           qp, kp, vp);

    // persistent attention + output projection (work-conserving backfill)
    attn_out_fused<<<nsm, 256, GEMM_SMEM_BYTES>>>(
        qp, kp, vp, op, w3, bo, out, order_gate, justice_gate, qptr);
}

// round 15
// speedup vs baseline: 1.0245x; 1.0245x over previous
#include <cuda_runtime.h>
#include <cuda_fp16.h>
#include <math.h>
#include <stdint.h>

#define SEQ   2048
#define HID   2048
#define HD    128
#define NH    16

// Scratch (device globals: allocation-free rule)
__device__ __half g_Qh[SEQ * HID];
__device__ __half g_Kh[SEQ * HID];
__device__ __half g_Vh[SEQ * HID];
__device__ __half g_Oh[SEQ * HID];
__device__ __half g_Xh[SEQ * HID];
__device__ __half g_W0h[HID * HID];
__device__ __half g_W1h[HID * HID];
__device__ __half g_W2h[HID * HID];
__device__ __half g_W3h[HID * HID];

// ===========================================================================
// Helpers
// ===========================================================================
__device__ __forceinline__ uint32_t smem_u32(const void* p) {
    uint32_t a;
    asm("{ .reg .u64 t; cvta.to.shared.u64 t, %1; cvt.u32.u64 %0, t; }"
        : "=r"(a) : "l"(p));
    return a;
}
__device__ __forceinline__ void cp_async16(uint32_t dst, const void* src) {
    asm volatile("cp.async.cg.shared.global [%0], [%1], 16;" :: "r"(dst), "l"(src));
}
#define CP_COMMIT() asm volatile("cp.async.commit_group;" ::: "memory")
#define CP_WAIT(n)  asm volatile("cp.async.wait_group %0;" :: "n"(n) : "memory")

__device__ __forceinline__ uint32_t pack_h2(float lo, float hi) {
    __half2 h = __floats2half2_rn(lo, hi);   // .x = lo (low 16 bits)
    return *(uint32_t*)&h;
}

// ldmatrix x4 b16 (native)
__device__ __forceinline__ void ldsm_x4(uint32_t r[4], uint32_t addr) {
    asm volatile("ldmatrix.sync.aligned.m8n8.x4.shared.b16 {%0,%1,%2,%3}, [%4];"
        : "=r"(r[0]), "=r"(r[1]), "=r"(r[2]), "=r"(r[3]) : "r"(addr));
}
__device__ __forceinline__ void ldsm_x4_t(uint32_t r[4], uint32_t addr) {
    asm volatile("ldmatrix.sync.aligned.m8n8.x4.trans.shared.b16 {%0,%1,%2,%3}, [%4];"
        : "=r"(r[0]), "=r"(r[1]), "=r"(r[2]), "=r"(r[3]) : "r"(addr));
}

// C[16x8] += A[16x16] * B[8x16]^T   (fp16 in, fp32 accum)
__device__ __forceinline__ void mma_f16(float c[4], const uint32_t a[4],
                                        const uint32_t b[2]) {
    asm volatile(
        "mma.sync.aligned.m16n8k16.row.col.f32.f16.f16.f32 "
        "{%0,%1,%2,%3}, {%4,%5,%6,%7}, {%8,%9}, {%0,%1,%2,%3};"
        : "+f"(c[0]), "+f"(c[1]), "+f"(c[2]), "+f"(c[3])
        : "r"(a[0]), "r"(a[1]), "r"(a[2]), "r"(a[3]), "r"(b[0]), "r"(b[1]));
}

// ===========================================================================
// Fused fp32 -> fp16 conversion prepass (5 tensors, one launch)
// ===========================================================================
__global__ __launch_bounds__(256) void cvt_f16_5(
    const float4* __restrict__ i0, const float4* __restrict__ i1,
    const float4* __restrict__ i2, const float4* __restrict__ i3,
    const float4* __restrict__ i4,
    __half* __restrict__ o0, __half* __restrict__ o1,
    __half* __restrict__ o2, __half* __restrict__ o3,
    __half* __restrict__ o4, int n4)
{
    const int z = blockIdx.y;
    const float4* in = (z == 0) ? i0 : (z == 1) ? i1 : (z == 2) ? i2
                      : (z == 3) ? i3 : i4;
    __half* out      = (z == 0) ? o0 : (z == 1) ? o1 : (z == 2) ? o2
                      : (z == 3) ? o3 : o4;
    int i = blockIdx.x * blockDim.x + threadIdx.x;
    if (i >= n4) return;
    float4 v = in[i];
    uint2 h;
    h.x = pack_h2(v.x, v.y);
    h.y = pack_h2(v.z, v.w);
    ((uint2*)out)[i] = h;
}

// ===========================================================================
// fp16 mma.sync GEMM core:  C[M,N] = A[M,K] @ B[N,K]^T + bias[N]
// CTA 128x256, 8 warps (2x4) of 64x64, BK=64 halfs, 3-stage cp.async,
// SINGLE __syncthreads per K-chunk (wait -> sync -> issue-next -> compute).
// HALF_OUT: store fp16 (feeds downstream fp16 MMAs); else fp32.
// ===========================================================================
#define BM 128
#define BN 256
#define BK 64
#define NST 3
#define ROWPH 72                            // halfs; 144B rows, conflict-free
#define ATFH (BM * ROWPH)                   // 9216 halfs
#define BTFH (BN * ROWPH)                   // 18432 halfs
#define STFH (ATFH + BTFH)                  // 27648 halfs = 55296 B / stage
#define GEMM_SMEM_BYTES (NST * STFH * 2)    // 165888

__device__ __forceinline__ void gemm_load_stage(
    const __half* __restrict__ Ab, const __half* __restrict__ Bb,
    __half* sm, int slot, int k0, int tid)
{
    const uint32_t sbase = smem_u32(sm) + (uint32_t)(slot * STFH) * 2u;
#pragma unroll
    for (int it = 0; it < 12; it++) {
        const int idx = tid + it * 256;       // 0..3071
        const int r = idx >> 3;               // 0..383
        const int q = idx & 7;                // 8-half (16B) segment
        const __half* src = (r < BM) ? (Ab + (size_t)r * HID + k0 + q * 8)
                                     : (Bb + (size_t)(r - BM) * HID + k0 + q * 8);
        cp_async16(sbase + (uint32_t)(r * ROWPH + q * 8) * 2u, src);
    }
}

template <bool HALF_OUT>
__device__ __forceinline__ void gemm_body(
    const __half* __restrict__ A, const __half* __restrict__ B,
    const float* __restrict__ bias, void* __restrict__ Cv,
    __half* sm, int row0, int col0)
{
    const int tid  = threadIdx.x;
    const int wid  = tid >> 5;
    const int lane = tid & 31;
    const int lr   = lane >> 2;
    const int lc   = lane & 3;
    const int l15  = lane & 15;
    const int klo  = (lane >> 4) << 3;     // 0 or 8 halfs
    const int wm   = (wid >> 2) * 64;
    const int wn   = (wid & 3) * 64;

    const __half* Ab = A + (size_t)row0 * HID;
    const __half* Bb = B + (size_t)col0 * HID;

    float acc[4][8][4];
#pragma unroll
    for (int mt = 0; mt < 4; mt++)
#pragma unroll
        for (int nt = 0; nt < 8; nt++)
#pragma unroll
            for (int i = 0; i < 4; i++) acc[mt][nt][i] = 0.0f;

#pragma unroll
    for (int s = 0; s < NST - 1; s++) {
        gemm_load_stage(Ab, Bb, sm, s, s * BK, tid);
        CP_COMMIT();
    }

    const uint32_t sbase = smem_u32(sm);
    const int KCH = HID / BK;   // 32
    for (int j = 0; j < KCH; j++) {
        CP_WAIT(NST - 2);         // chunk j resident
        __syncthreads();          // all warps done reading slot (j+NST-1)%NST
        if (j + NST - 1 < KCH) {
            gemm_load_stage(Ab, Bb, sm, (j + NST - 1) % NST, (j + NST - 1) * BK, tid);
        }
        CP_COMMIT();              // may be empty near the tail (keeps group math exact)

        const uint32_t sa = sbase + (uint32_t)((j % NST) * STFH) * 2u;
        const uint32_t sb = sa + (uint32_t)ATFH * 2u;

#pragma unroll
        for (int kk = 0; kk < BK; kk += 16) {
            uint32_t af[4][4], bf[8][2];
#pragma unroll
            for (int mt = 0; mt < 4; mt++)
                ldsm_x4(af[mt],
                        sa + (uint32_t)((wm + mt * 16 + l15) * ROWPH + kk + klo) * 2u);
#pragma unroll
            for (int np = 0; np < 4; np++) {
                uint32_t t[4];
                ldsm_x4(t,
                        sb + (uint32_t)((wn + np * 16 + l15) * ROWPH + kk + klo) * 2u);
                bf[2 * np + 0][0] = t[0];
                bf[2 * np + 1][0] = t[1];
                bf[2 * np + 0][1] = t[2];
                bf[2 * np + 1][1] = t[3];
            }
#pragma unroll
            for (int mt = 0; mt < 4; mt++)
#pragma unroll
                for (int nt = 0; nt < 8; nt++)
                    mma_f16(acc[mt][nt], af[mt], bf[nt]);
        }
    }

#pragma unroll
    for (int mt = 0; mt < 4; mt++) {
#pragma unroll
        for (int half = 0; half < 2; half++) {
            const int r = row0 + wm + mt * 16 + lr + half * 8;
#pragma unroll
            for (int nt = 0; nt < 8; nt++) {
                const int c = col0 + wn + nt * 8 + 2 * lc;
                const float vx = acc[mt][nt][half * 2 + 0] + bias[c];
                const float vy = acc[mt][nt][half * 2 + 1] + bias[c + 1];
                if (HALF_OUT) {
                    __half* crow = (__half*)Cv + (size_t)r * HID;
                    *(uint32_t*)(crow + c) = pack_h2(vx, vy);
                } else {
                    float* crow = (float*)Cv + (size_t)r * HID;
                    *(float2*)(crow + c) = make_float2(vx, vy);
                }
            }
        }
    }
}

// Fused QKV projection: blockIdx.z selects weight/bias/output.
__global__ __launch_bounds__(256, 1) void gemm_qkv(
    const __half* __restrict__ A,
    const __half* __restrict__ W0, const __half* __restrict__ W1,
    const __half* __restrict__ W2,
    const float* __restrict__ b0, const float* __restrict__ b1,
    const float* __restrict__ b2,
    __half* __restrict__ C0, __half* __restrict__ C1, __half* __restrict__ C2)
{
    extern __shared__ __half smh[];
    const int z = blockIdx.z;
    const __half* B   = (z == 0) ? W0 : (z == 1) ? W1 : W2;
    const float* bias = (z == 0) ? b0 : (z == 1) ? b1 : b2;
    __half* C         = (z == 0) ? C0 : (z == 1) ? C1 : C2;
    gemm_body<true>(A, B, bias, C, smh, blockIdx.y * BM, blockIdx.x * BN);
}

// Output projection (fp32 result)
__global__ __launch_bounds__(256, 1) void gemm_single(
    const __half* __restrict__ A, const __half* __restrict__ B,
    const float* __restrict__ bias, float* __restrict__ C)
{
    extern __shared__ __half smh[];
    gemm_body<false>(A, B, bias, C, smh, blockIdx.y * BM, blockIdx.x * BN);
}

// ===========================================================================
// Flash attention, fp16 mma.sync (m16n8k16).
// 1 CTA = 128 q-rows x 1 head, 8 warps, each warp 16 q-rows end-to-end.
// 3-slot KV ring, SINGLE __syncthreads per tile.
// K via ldmatrix.x4 (n-major); V via ldmatrix.x4.trans (k-major).
// ===========================================================================
#define FAQ 128
#define FSK 64
#define FSTG 3
#define KPH 136                       // halfs: 272B rows, conflict-free
#define KTILEH (FSK * KPH)            // 8704 halfs = 17408 B
#define FSTAGEH (2 * KTILEH)          // K + V : 34816 B
#define FLASH_SMEM_BYTES (FSTG * FSTAGEH * 2)   // 104448

__device__ __forceinline__ void flash_load_kv(
    const __half* __restrict__ K, const __half* __restrict__ V,
    __half* sm, int slot, int kt, int hcol, int tid)
{
    const uint32_t ka = smem_u32(sm) + (uint32_t)(slot * FSTAGEH) * 2u;
    const uint32_t va = ka + (uint32_t)KTILEH * 2u;
    const int base = kt * FSK;
#pragma unroll
    for (int it = 0; it < 4; it++) {
        const int idx = tid + it * 256;     // 0..1023
        const int r = idx >> 4;             // 0..63
        const int q = idx & 15;             // 8-half segments
        cp_async16(ka + (uint32_t)(r * KPH + q * 8) * 2u,
                   K + (size_t)(base + r) * HID + hcol + q * 8);
        cp_async16(va + (uint32_t)(r * KPH + q * 8) * 2u,
                   V + (size_t)(base + r) * HID + hcol + q * 8);
    }
}

__global__ __launch_bounds__(256, 1) void flash_attn_f16(
    const __half* __restrict__ Q, const __half* __restrict__ K,
    const __half* __restrict__ V, __half* __restrict__ O,
    const float* __restrict__ order_gate, const float* __restrict__ justice_gate)
{
    extern __shared__ __half fsmh[];

    const int tid  = threadIdx.x;
    const int wid  = tid >> 5;
    const int lane = tid & 31;
    const int lr   = lane >> 2;
    const int lc   = lane & 3;
    const int l15  = lane & 15;
    const int klo  = (lane >> 4) << 3;
    const int hcol = blockIdx.y * HD;
    const int qbase = blockIdx.x * FAQ + wid * 16;

    const float sig_j = 1.0f / (1.0f + __expf(-justice_gate[0]));
    const float sig_o = 1.0f / (1.0f + __expf(-order_gate[0]));
    const float alpha = (1.0f - 0.1f * sig_j) * rsqrtf((float)HD);
    const float obias = sig_o * 0.05f / (float)SEQ;

    // Q fragments (8 k16 chunks), register-resident, loaded straight from gmem
    uint32_t qf[8][4];
    {
        const __half* Qb = Q + (size_t)qbase * HID + hcol;
#pragma unroll
        for (int ks = 0; ks < 8; ks++) {
            qf[ks][0] = *(const uint32_t*)(Qb + (size_t)lr * HID + ks * 16 + 2 * lc);
            qf[ks][1] = *(const uint32_t*)(Qb + (size_t)(lr + 8) * HID + ks * 16 + 2 * lc);
            qf[ks][2] = *(const uint32_t*)(Qb + (size_t)lr * HID + ks * 16 + 2 * lc + 8);
            qf[ks][3] = *(const uint32_t*)(Qb + (size_t)(lr + 8) * HID + ks * 16 + 2 * lc + 8);
        }
    }

    float m0 = -1.0e30f, m1 = -1.0e30f, l0 = 0.0f, l1 = 0.0f;
    float of[16][4];
#pragma unroll
    for (int nt = 0; nt < 16; nt++)
#pragma unroll
        for (int i = 0; i < 4; i++) of[nt][i] = 0.0f;

    flash_load_kv(K, V, fsmh, 0, 0, hcol, tid);
    CP_COMMIT();
    flash_load_kv(K, V, fsmh, 1, 1, hcol, tid);
    CP_COMMIT();

    const int NT = SEQ / FSK;   // 32
    for (int kt = 0; kt < NT; kt++) {
        CP_WAIT(1);             // tile kt resident
        __syncthreads();        // all warps done reading slot (kt+2)%FSTG
        if (kt + 2 < NT) {
            flash_load_kv(K, V, fsmh, (kt + 2) % FSTG, kt + 2, hcol, tid);
        }
        CP_COMMIT();            // may be empty near the tail

        const uint32_t ksa = smem_u32(fsmh) + (uint32_t)((kt % FSTG) * FSTAGEH) * 2u;
        const uint32_t vsa = ksa + (uint32_t)KTILEH * 2u;

        // S = Q K^T : 8 k16 steps over d=128
        float sf[8][4];
#pragma unroll
        for (int nt = 0; nt < 8; nt++)
#pragma unroll
            for (int i = 0; i < 4; i++) sf[nt][i] = 0.0f;

#pragma unroll
        for (int ks = 0; ks < 8; ks++) {
            uint32_t bf[8][2];
#pragma unroll
            for (int np = 0; np < 4; np++) {
                uint32_t t[4];
                ldsm_x4(t, ksa + (uint32_t)((np * 16 + l15) * KPH + ks * 16 + klo) * 2u);
                bf[2 * np + 0][0] = t[0];
                bf[2 * np + 1][0] = t[1];
                bf[2 * np + 0][1] = t[2];
                bf[2 * np + 1][1] = t[3];
            }
#pragma unroll
            for (int nt = 0; nt < 8; nt++)
                mma_f16(sf[nt], qf[ks], bf[nt]);
        }

        // scale + key position bias; row max
        float rmax0 = -1.0e30f, rmax1 = -1.0e30f;
#pragma unroll
        for (int nt = 0; nt < 8; nt++) {
            const float col0 = (float)(kt * FSK + nt * 8 + 2 * lc);
            sf[nt][0] = fmaf(sf[nt][0], alpha, obias * col0);
            sf[nt][1] = fmaf(sf[nt][1], alpha, obias * (col0 + 1.0f));
            sf[nt][2] = fmaf(sf[nt][2], alpha, obias * col0);
            sf[nt][3] = fmaf(sf[nt][3], alpha, obias * (col0 + 1.0f));
            rmax0 = fmaxf(rmax0, fmaxf(sf[nt][0], sf[nt][1]));
            rmax1 = fmaxf(rmax1, fmaxf(sf[nt][2], sf[nt][3]));
        }
#pragma unroll
        for (int off = 1; off < 4; off <<= 1) {
            rmax0 = fmaxf(rmax0, __shfl_xor_sync(0xffffffffu, rmax0, off));
            rmax1 = fmaxf(rmax1, __shfl_xor_sync(0xffffffffu, rmax1, off));
        }
        const float m0n = fmaxf(m0, rmax0);
        const float m1n = fmaxf(m1, rmax1);
        const float corr0 = __expf(m0 - m0n);
        const float corr1 = __expf(m1 - m1n);

        // exp + row sums + fp16 P fragments (in-thread pack, no shuffles)
        float rsum0 = 0.0f, rsum1 = 0.0f;
        uint32_t ph[8][2];
#pragma unroll
        for (int nt = 0; nt < 8; nt++) {
            const float e0 = __expf(sf[nt][0] - m0n);
            const float e1 = __expf(sf[nt][1] - m0n);
            const float e2 = __expf(sf[nt][2] - m1n);
            const float e3 = __expf(sf[nt][3] - m1n);
            rsum0 += e0 + e1;
            rsum1 += e2 + e3;
            ph[nt][0] = pack_h2(e0, e1);   // row lr,   keys {nt*8+2lc, +1}
            ph[nt][1] = pack_h2(e2, e3);   // row lr+8, same keys
        }
#pragma unroll
        for (int off = 1; off < 4; off <<= 1) {
            rsum0 += __shfl_xor_sync(0xffffffffu, rsum0, off);
            rsum1 += __shfl_xor_sync(0xffffffffu, rsum1, off);
        }
        l0 = l0 * corr0 + rsum0; m0 = m0n;
        l1 = l1 * corr1 + rsum1; m1 = m1n;

#pragma unroll
        for (int nt = 0; nt < 16; nt++) {
            of[nt][0] *= corr0; of[nt][1] *= corr0;
            of[nt][2] *= corr1; of[nt][3] *= corr1;
        }

        // O += P V : 4 k16 chunks over 64 keys; V via ldmatrix.trans
#pragma unroll
        for (int kp = 0; kp < 4; kp++) {
            uint32_t pa[4];
            pa[0] = ph[2 * kp + 0][0];
            pa[1] = ph[2 * kp + 0][1];
            pa[2] = ph[2 * kp + 1][0];
            pa[3] = ph[2 * kp + 1][1];
#pragma unroll
            for (int dg = 0; dg < 8; dg++) {
                uint32_t t[4];
                ldsm_x4_t(t, vsa + (uint32_t)((kp * 16 + l15) * KPH + dg * 16 + klo) * 2u);
                uint32_t b0[2] = {t[0], t[1]};
                uint32_t b1[2] = {t[2], t[3]};
                mma_f16(of[2 * dg + 0], pa, b0);
                mma_f16(of[2 * dg + 1], pa, b1);
            }
        }
    }

    // normalize + fp16 write (feeds final fp16 GEMM)
    const float invl0 = 1.0f / l0;
    const float invl1 = 1.0f / l1;
    __half* Ob = O + (size_t)qbase * HID + hcol;
#pragma unroll
    for (int nt = 0; nt < 16; nt++) {
        const int c = nt * 8 + 2 * lc;
        *(uint32_t*)(Ob + (size_t)lr * HID + c) =
            pack_h2(of[nt][0] * invl0, of[nt][1] * invl0);
        *(uint32_t*)(Ob + (size_t)(lr + 8) * HID + c) =
            pack_h2(of[nt][2] * invl1, of[nt][3] * invl1);
    }
}

// ===========================================================================
extern "C" void kernel_launch(void* const* d_in, const int* in_sizes, int n_in,
                              void* d_out, int out_size)
{
    const float* X  = (const float*)d_in[0];
    const float* Wq = (const float*)d_in[1];
    const float* bq = (const float*)d_in[2];
    const float* Wk = (const float*)d_in[3];
    const float* bk = (const float*)d_in[4];
    const float* Wv = (const float*)d_in[5];
    const float* bv = (const float*)d_in[6];
    const float* Wo = (const float*)d_in[7];
    const float* bo = (const float*)d_in[8];
    const float* order_gate   = (const float*)d_in[11];
    const float* justice_gate = (const float*)d_in[12];
    float* out = (float*)d_out;

    __half *qp, *kp, *vp, *op, *xh, *w0, *w1, *w2, *w3;
    cudaGetSymbolAddress((void**)&qp, g_Qh);
    cudaGetSymbolAddress((void**)&kp, g_Kh);
    cudaGetSymbolAddress((void**)&vp, g_Vh);
    cudaGetSymbolAddress((void**)&op, g_Oh);
    cudaGetSymbolAddress((void**)&xh, g_Xh);
    cudaGetSymbolAddress((void**)&w0, g_W0h);
    cudaGetSymbolAddress((void**)&w1, g_W1h);
    cudaGetSymbolAddress((void**)&w2, g_W2h);
    cudaGetSymbolAddress((void**)&w3, g_W3h);

    cudaFuncSetAttribute(gemm_qkv,
                         cudaFuncAttributeMaxDynamicSharedMemorySize,
                         GEMM_SMEM_BYTES);
    cudaFuncSetAttribute(gemm_single,
                         cudaFuncAttributeMaxDynamicSharedMemorySize,
                         GEMM_SMEM_BYTES);
    cudaFuncSetAttribute(flash_attn_f16,
                         cudaFuncAttributeMaxDynamicSharedMemorySize,
                         FLASH_SMEM_BYTES);

    const int N4 = (HID * HID) / 4;

    // fused prepass: convert all 5 fp32 inputs to fp16 in one launch
    dim3 rg((N4 + 255) / 256, 5);
    cvt_f16_5<<<rg, 256>>>((const float4*)X,  (const float4*)Wq,
                           (const float4*)Wk, (const float4*)Wv,
                           (const float4*)Wo,
                           xh, w0, w1, w2, w3, N4);

    // fused QKV projections (one launch, z = 0/1/2)
    dim3 gq(HID / BN, SEQ / BM, 3);   // 8 x 16 x 3
    gemm_qkv<<<gq, 256, GEMM_SMEM_BYTES>>>(xh, w0, w1, w2, bq, bk, bv,
                                           qp, kp, vp);

    dim3 ga(SEQ / FAQ, NH);           // 16 x 16
    flash_attn_f16<<<ga, 256, FLASH_SMEM_BYTES>>>(qp, kp, vp, op,
                                                  order_gate, justice_gate);

    dim3 gg(HID / BN, SEQ / BM);      // 8 x 16
    gemm_single<<<gg, 256, GEMM_SMEM_BYTES>>>(op, w3, bo, out);
}

// round 16
// speedup vs baseline: 1.0335x; 1.0088x over previous
#include <cuda_runtime.h>
#include <cuda_fp16.h>
#include <math.h>
#include <stdint.h>

#define SEQ   2048
#define HID   2048
#define HD    128
#define NH    16

// Scratch (device globals: allocation-free rule)
__device__ __half g_Qh[SEQ * HID];
__device__ __half g_Kh[SEQ * HID];
__device__ __half g_Vh[SEQ * HID];
__device__ __half g_Oh[SEQ * HID];
__device__ __half g_Xh[SEQ * HID];
__device__ __half g_W0h[HID * HID];
__device__ __half g_W1h[HID * HID];
__device__ __half g_W2h[HID * HID];
__device__ __half g_W3h[HID * HID];

// ===========================================================================
// Helpers
// ===========================================================================
__device__ __forceinline__ uint32_t smem_u32(const void* p) {
    uint32_t a;
    asm("{ .reg .u64 t; cvta.to.shared.u64 t, %1; cvt.u32.u64 %0, t; }"
        : "=r"(a) : "l"(p));
    return a;
}
__device__ __forceinline__ void cp_async16(uint32_t dst, const void* src) {
    asm volatile("cp.async.cg.shared.global [%0], [%1], 16;" :: "r"(dst), "l"(src));
}
#define CP_COMMIT() asm volatile("cp.async.commit_group;" ::: "memory")
#define CP_WAIT(n)  asm volatile("cp.async.wait_group %0;" :: "n"(n) : "memory")

__device__ __forceinline__ uint32_t pack_h2(float lo, float hi) {
    __half2 h = __floats2half2_rn(lo, hi);   // .x = lo (low 16 bits)
    return *(uint32_t*)&h;
}

// ldmatrix x4 b16 (native)
__device__ __forceinline__ void ldsm_x4(uint32_t r[4], uint32_t addr) {
    asm volatile("ldmatrix.sync.aligned.m8n8.x4.shared.b16 {%0,%1,%2,%3}, [%4];"
        : "=r"(r[0]), "=r"(r[1]), "=r"(r[2]), "=r"(r[3]) : "r"(addr));
}
__device__ __forceinline__ void ldsm_x4_t(uint32_t r[4], uint32_t addr) {
    asm volatile("ldmatrix.sync.aligned.m8n8.x4.trans.shared.b16 {%0,%1,%2,%3}, [%4];"
        : "=r"(r[0]), "=r"(r[1]), "=r"(r[2]), "=r"(r[3]) : "r"(addr));
}

// C[16x8] += A[16x16] * B[8x16]^T   (fp16 in, fp32 accum)
__device__ __forceinline__ void mma_f16(float c[4], const uint32_t a[4],
                                        const uint32_t b[2]) {
    asm volatile(
        "mma.sync.aligned.m16n8k16.row.col.f32.f16.f16.f32 "
        "{%0,%1,%2,%3}, {%4,%5,%6,%7}, {%8,%9}, {%0,%1,%2,%3};"
        : "+f"(c[0]), "+f"(c[1]), "+f"(c[2]), "+f"(c[3])
        : "r"(a[0]), "r"(a[1]), "r"(a[2]), "r"(a[3]), "r"(b[0]), "r"(b[1]));
}

// ===========================================================================
// Fused fp32 -> fp16 conversion prepass (4 tensors: X, Wq, Wk, Wv).
// Wo is converted inside the gemm_qkv launch (z==3 slice) where it overlaps
// the qkv GEMM's partial third wave.
// ===========================================================================
__global__ __launch_bounds__(256) void cvt_f16_4(
    const float4* __restrict__ i0, const float4* __restrict__ i1,
    const float4* __restrict__ i2, const float4* __restrict__ i3,
    __half* __restrict__ o0, __half* __restrict__ o1,
    __half* __restrict__ o2, __half* __restrict__ o3, int n4)
{
    const int z = blockIdx.y;
    const float4* in = (z == 0) ? i0 : (z == 1) ? i1 : (z == 2) ? i2 : i3;
    __half* out      = (z == 0) ? o0 : (z == 1) ? o1 : (z == 2) ? o2 : o3;
    int i = blockIdx.x * blockDim.x + threadIdx.x;
    if (i >= n4) return;
    float4 v = in[i];
    uint2 h;
    h.x = pack_h2(v.x, v.y);
    h.y = pack_h2(v.z, v.w);
    ((uint2*)out)[i] = h;
}

// ===========================================================================
// fp16 mma.sync GEMM core:  C[M,N] = A[M,K] @ B[N,K]^T + bias[N]
// CTA 128x256, 8 warps (2x4) of 64x64, BK=64 halfs, 3-stage cp.async,
// SINGLE __syncthreads per K-chunk (wait -> sync -> issue-next -> compute).
// HALF_OUT: store fp16 (feeds downstream fp16 MMAs); else fp32.
// ===========================================================================
#define BM 128
#define BN 256
#define BK 64
#define NST 3
#define ROWPH 72                            // halfs; 144B rows, conflict-free
#define ATFH (BM * ROWPH)                   // 9216 halfs
#define BTFH (BN * ROWPH)                   // 18432 halfs
#define STFH (ATFH + BTFH)                  // 27648 halfs = 55296 B / stage
#define GEMM_SMEM_BYTES (NST * STFH * 2)    // 165888

__device__ __forceinline__ void gemm_load_stage(
    const __half* __restrict__ Ab, const __half* __restrict__ Bb,
    __half* sm, int slot, int k0, int tid)
{
    const uint32_t sbase = smem_u32(sm) + (uint32_t)(slot * STFH) * 2u;
#pragma unroll
    for (int it = 0; it < 12; it++) {
        const int idx = tid + it * 256;       // 0..3071
        const int r = idx >> 3;               // 0..383
        const int q = idx & 7;                // 8-half (16B) segment
        const __half* src = (r < BM) ? (Ab + (size_t)r * HID + k0 + q * 8)
                                     : (Bb + (size_t)(r - BM) * HID + k0 + q * 8);
        cp_async16(sbase + (uint32_t)(r * ROWPH + q * 8) * 2u, src);
    }
}

template <bool HALF_OUT>
__device__ __forceinline__ void gemm_body(
    const __half* __restrict__ A, const __half* __restrict__ B,
    const float* __restrict__ bias, void* __restrict__ Cv,
    __half* sm, int row0, int col0)
{
    const int tid  = threadIdx.x;
    const int wid  = tid >> 5;
    const int lane = tid & 31;
    const int lr   = lane >> 2;
    const int lc   = lane & 3;
    const int l15  = lane & 15;
    const int klo  = (lane >> 4) << 3;     // 0 or 8 halfs
    const int wm   = (wid >> 2) * 64;
    const int wn   = (wid & 3) * 64;

    const __half* Ab = A + (size_t)row0 * HID;
    const __half* Bb = B + (size_t)col0 * HID;

    float acc[4][8][4];
#pragma unroll
    for (int mt = 0; mt < 4; mt++)
#pragma unroll
        for (int nt = 0; nt < 8; nt++)
#pragma unroll
            for (int i = 0; i < 4; i++) acc[mt][nt][i] = 0.0f;

#pragma unroll
    for (int s = 0; s < NST - 1; s++) {
        gemm_load_stage(Ab, Bb, sm, s, s * BK, tid);
        CP_COMMIT();
    }

    const uint32_t sbase = smem_u32(sm);
    const int KCH = HID / BK;   // 32
    for (int j = 0; j < KCH; j++) {
        CP_WAIT(NST - 2);         // chunk j resident
        __syncthreads();          // all warps done reading slot (j+NST-1)%NST
        if (j + NST - 1 < KCH) {
            gemm_load_stage(Ab, Bb, sm, (j + NST - 1) % NST, (j + NST - 1) * BK, tid);
        }
        CP_COMMIT();              // may be empty near the tail (keeps group math exact)

        const uint32_t sa = sbase + (uint32_t)((j % NST) * STFH) * 2u;
        const uint32_t sb = sa + (uint32_t)ATFH * 2u;

#pragma unroll
        for (int kk = 0; kk < BK; kk += 16) {
            uint32_t af[4][4], bf[8][2];
#pragma unroll
            for (int mt = 0; mt < 4; mt++)
                ldsm_x4(af[mt],
                        sa + (uint32_t)((wm + mt * 16 + l15) * ROWPH + kk + klo) * 2u);
#pragma unroll
            for (int np = 0; np < 4; np++) {
                uint32_t t[4];
                ldsm_x4(t,
                        sb + (uint32_t)((wn + np * 16 + l15) * ROWPH + kk + klo) * 2u);
                bf[2 * np + 0][0] = t[0];
                bf[2 * np + 1][0] = t[1];
                bf[2 * np + 0][1] = t[2];
                bf[2 * np + 1][1] = t[3];
            }
#pragma unroll
            for (int mt = 0; mt < 4; mt++)
#pragma unroll
                for (int nt = 0; nt < 8; nt++)
                    mma_f16(acc[mt][nt], af[mt], bf[nt]);
        }
    }

#pragma unroll
    for (int mt = 0; mt < 4; mt++) {
#pragma unroll
        for (int half = 0; half < 2; half++) {
            const int r = row0 + wm + mt * 16 + lr + half * 8;
#pragma unroll
            for (int nt = 0; nt < 8; nt++) {
                const int c = col0 + wn + nt * 8 + 2 * lc;
                const float vx = acc[mt][nt][half * 2 + 0] + bias[c];
                const float vy = acc[mt][nt][half * 2 + 1] + bias[c + 1];
                if (HALF_OUT) {
                    __half* crow = (__half*)Cv + (size_t)r * HID;
                    *(uint32_t*)(crow + c) = pack_h2(vx, vy);
                } else {
                    float* crow = (float*)Cv + (size_t)r * HID;
                    *(float2*)(crow + c) = make_float2(vx, vy);
                }
            }
        }
    }
}

// Fused QKV projection + Wo conversion: blockIdx.z = 0/1/2 -> GEMM tile;
// blockIdx.z = 3 -> convert one 1/128 chunk of Wo fp32 -> fp16 (these light
// CTAs dispatch last and fill the GEMM's partial third wave).
__global__ __launch_bounds__(256, 1) void gemm_qkv(
    const __half* __restrict__ A,
    const __half* __restrict__ W0, const __half* __restrict__ W1,
    const __half* __restrict__ W2,
    const float* __restrict__ b0, const float* __restrict__ b1,
    const float* __restrict__ b2,
    __half* __restrict__ C0, __half* __restrict__ C1, __half* __restrict__ C2,
    const float4* __restrict__ WoF, __half* __restrict__ WoH)
{
    extern __shared__ __half smh[];
    const int z = blockIdx.z;
    if (z == 3) {
        // convert Wo chunk: 128 CTAs x 8192 float4 (= HID*HID/4 total)
        const int chunk = blockIdx.y * 8 + blockIdx.x;    // 0..127
        const int base  = chunk * 8192;
#pragma unroll
        for (int it = 0; it < 32; it++) {
            const int i = base + it * 256 + threadIdx.x;
            float4 v = WoF[i];
            uint2 h;
            h.x = pack_h2(v.x, v.y);
            h.y = pack_h2(v.z, v.w);
            ((uint2*)WoH)[i] = h;
        }
        return;
    }
    const __half* B   = (z == 0) ? W0 : (z == 1) ? W1 : W2;
    const float* bias = (z == 0) ? b0 : (z == 1) ? b1 : b2;
    __half* C         = (z == 0) ? C0 : (z == 1) ? C1 : C2;
    gemm_body<true>(A, B, bias, C, smh, blockIdx.y * BM, blockIdx.x * BN);
}

// Output projection (fp32 result)
__global__ __launch_bounds__(256, 1) void gemm_single(
    const __half* __restrict__ A, const __half* __restrict__ B,
    const float* __restrict__ bias, float* __restrict__ C)
{
    extern __shared__ __half smh[];
    gemm_body<false>(A, B, bias, C, smh, blockIdx.y * BM, blockIdx.x * BN);
}

// ===========================================================================
// Flash attention, fp16 mma.sync (m16n8k16).
// 1 CTA = 128 q-rows x 1 head, 8 warps, each warp 16 q-rows end-to-end.
// 3-slot KV ring, SINGLE __syncthreads per tile.
// K via ldmatrix.x4 (n-major); V via ldmatrix.x4.trans (k-major).
// ===========================================================================
#define FAQ 128
#define FSK 64
#define FSTG 3
#define KPH 136                       // halfs: 272B rows, conflict-free
#define KTILEH (FSK * KPH)            // 8704 halfs = 17408 B
#define FSTAGEH (2 * KTILEH)          // K + V : 34816 B
#define FLASH_SMEM_BYTES (FSTG * FSTAGEH * 2)   // 104448

__device__ __forceinline__ void flash_load_kv(
    const __half* __restrict__ K, const __half* __restrict__ V,
    __half* sm, int slot, int kt, int hcol, int tid)
{
    const uint32_t ka = smem_u32(sm) + (uint32_t)(slot * FSTAGEH) * 2u;
    const uint32_t va = ka + (uint32_t)KTILEH * 2u;
    const int base = kt * FSK;
#pragma unroll
    for (int it = 0; it < 4; it++) {
        const int idx = tid + it * 256;     // 0..1023
        const int r = idx >> 4;             // 0..63
        const int q = idx & 15;             // 8-half segments
        cp_async16(ka + (uint32_t)(r * KPH + q * 8) * 2u,
                   K + (size_t)(base + r) * HID + hcol + q * 8);
        cp_async16(va + (uint32_t)(r * KPH + q * 8) * 2u,
                   V + (size_t)(base + r) * HID + hcol + q * 8);
    }
}

__global__ __launch_bounds__(256, 1) void flash_attn_f16(
    const __half* __restrict__ Q, const __half* __restrict__ K,
    const __half* __restrict__ V, __half* __restrict__ O,
    const float* __restrict__ order_gate, const float* __restrict__ justice_gate)
{
    extern __shared__ __half fsmh[];

    const int tid  = threadIdx.x;
    const int wid  = tid >> 5;
    const int lane = tid & 31;
    const int lr   = lane >> 2;
    const int lc   = lane & 3;
    const int l15  = lane & 15;
    const int klo  = (lane >> 4) << 3;
    const int hcol = blockIdx.y * HD;
    const int qbase = blockIdx.x * FAQ + wid * 16;

    const float sig_j = 1.0f / (1.0f + __expf(-justice_gate[0]));
    const float sig_o = 1.0f / (1.0f + __expf(-order_gate[0]));
    const float alpha = (1.0f - 0.1f * sig_j) * rsqrtf((float)HD);
    const float obias = sig_o * 0.05f / (float)SEQ;

    // Q fragments (8 k16 chunks), register-resident, loaded straight from gmem
    uint32_t qf[8][4];
    {
        const __half* Qb = Q + (size_t)qbase * HID + hcol;
#pragma unroll
        for (int ks = 0; ks < 8; ks++) {
            qf[ks][0] = *(const uint32_t*)(Qb + (size_t)lr * HID + ks * 16 + 2 * lc);
            qf[ks][1] = *(const uint32_t*)(Qb + (size_t)(lr + 8) * HID + ks * 16 + 2 * lc);
            qf[ks][2] = *(const uint32_t*)(Qb + (size_t)lr * HID + ks * 16 + 2 * lc + 8);
            qf[ks][3] = *(const uint32_t*)(Qb + (size_t)(lr + 8) * HID + ks * 16 + 2 * lc + 8);
        }
    }

    float m0 = -1.0e30f, m1 = -1.0e30f, l0 = 0.0f, l1 = 0.0f;
    float of[16][4];
#pragma unroll
    for (int nt = 0; nt < 16; nt++)
#pragma unroll
        for (int i = 0; i < 4; i++) of[nt][i] = 0.0f;

    flash_load_kv(K, V, fsmh, 0, 0, hcol, tid);
    CP_COMMIT();
    flash_load_kv(K, V, fsmh, 1, 1, hcol, tid);
    CP_COMMIT();

    const int NT = SEQ / FSK;   // 32
    for (int kt = 0; kt < NT; kt++) {
        CP_WAIT(1);             // tile kt resident
        __syncthreads();        // all warps done reading slot (kt+2)%FSTG
        if (kt + 2 < NT) {
            flash_load_kv(K, V, fsmh, (kt + 2) % FSTG, kt + 2, hcol, tid);
        }
        CP_COMMIT();            // may be empty near the tail

        const uint32_t ksa = smem_u32(fsmh) + (uint32_t)((kt % FSTG) * FSTAGEH) * 2u;
        const uint32_t vsa = ksa + (uint32_t)KTILEH * 2u;

        // S = Q K^T : 8 k16 steps over d=128
        float sf[8][4];
#pragma unroll
        for (int nt = 0; nt < 8; nt++)
#pragma unroll
            for (int i = 0; i < 4; i++) sf[nt][i] = 0.0f;

#pragma unroll
        for (int ks = 0; ks < 8; ks++) {
            uint32_t bf[8][2];
#pragma unroll
            for (int np = 0; np < 4; np++) {
                uint32_t t[4];
                ldsm_x4(t, ksa + (uint32_t)((np * 16 + l15) * KPH + ks * 16 + klo) * 2u);
                bf[2 * np + 0][0] = t[0];
                bf[2 * np + 1][0] = t[1];
                bf[2 * np + 0][1] = t[2];
                bf[2 * np + 1][1] = t[3];
            }
#pragma unroll
            for (int nt = 0; nt < 8; nt++)
                mma_f16(sf[nt], qf[ks], bf[nt]);
        }

        // scale + key position bias; row max
        float rmax0 = -1.0e30f, rmax1 = -1.0e30f;
#pragma unroll
        for (int nt = 0; nt < 8; nt++) {
            const float col0 = (float)(kt * FSK + nt * 8 + 2 * lc);
            sf[nt][0] = fmaf(sf[nt][0], alpha, obias * col0);
            sf[nt][1] = fmaf(sf[nt][1], alpha, obias * (col0 + 1.0f));
            sf[nt][2] = fmaf(sf[nt][2], alpha, obias * col0);
            sf[nt][3] = fmaf(sf[nt][3], alpha, obias * (col0 + 1.0f));
            rmax0 = fmaxf(rmax0, fmaxf(sf[nt][0], sf[nt][1]));
            rmax1 = fmaxf(rmax1, fmaxf(sf[nt][2], sf[nt][3]));
        }
#pragma unroll
        for (int off = 1; off < 4; off <<= 1) {
            rmax0 = fmaxf(rmax0, __shfl_xor_sync(0xffffffffu, rmax0, off));
            rmax1 = fmaxf(rmax1, __shfl_xor_sync(0xffffffffu, rmax1, off));
        }
        const float m0n = fmaxf(m0, rmax0);
        const float m1n = fmaxf(m1, rmax1);
        const float corr0 = __expf(m0 - m0n);
        const float corr1 = __expf(m1 - m1n);

        // exp + row sums + fp16 P fragments (in-thread pack, no shuffles)
        float rsum0 = 0.0f, rsum1 = 0.0f;
        uint32_t ph[8][2];
#pragma unroll
        for (int nt = 0; nt < 8; nt++) {
            const float e0 = __expf(sf[nt][0] - m0n);
            const float e1 = __expf(sf[nt][1] - m0n);
            const float e2 = __expf(sf[nt][2] - m1n);
            const float e3 = __expf(sf[nt][3] - m1n);
            rsum0 += e0 + e1;
            rsum1 += e2 + e3;
            ph[nt][0] = pack_h2(e0, e1);   // row lr,   keys {nt*8+2lc, +1}
            ph[nt][1] = pack_h2(e2, e3);   // row lr+8, same keys
        }
#pragma unroll
        for (int off = 1; off < 4; off <<= 1) {
            rsum0 += __shfl_xor_sync(0xffffffffu, rsum0, off);
            rsum1 += __shfl_xor_sync(0xffffffffu, rsum1, off);
        }
        l0 = l0 * corr0 + rsum0; m0 = m0n;
        l1 = l1 * corr1 + rsum1; m1 = m1n;

#pragma unroll
        for (int nt = 0; nt < 16; nt++) {
            of[nt][0] *= corr0; of[nt][1] *= corr0;
            of[nt][2] *= corr1; of[nt][3] *= corr1;
        }

        // O += P V : 4 k16 chunks over 64 keys; V via ldmatrix.trans
#pragma unroll
        for (int kp = 0; kp < 4; kp++) {
            uint32_t pa[4];
            pa[0] = ph[2 * kp + 0][0];
            pa[1] = ph[2 * kp + 0][1];
            pa[2] = ph[2 * kp + 1][0];
            pa[3] = ph[2 * kp + 1][1];
#pragma unroll
            for (int dg = 0; dg < 8; dg++) {
                uint32_t t[4];
                ldsm_x4_t(t, vsa + (uint32_t)((kp * 16 + l15) * KPH + dg * 16 + klo) * 2u);
                uint32_t b0[2] = {t[0], t[1]};
                uint32_t b1[2] = {t[2], t[3]};
                mma_f16(of[2 * dg + 0], pa, b0);
                mma_f16(of[2 * dg + 1], pa, b1);
            }
        }
    }

    // normalize + fp16 write (feeds final fp16 GEMM)
    const float invl0 = 1.0f / l0;
    const float invl1 = 1.0f / l1;
    __half* Ob = O + (size_t)qbase * HID + hcol;
#pragma unroll
    for (int nt = 0; nt < 16; nt++) {
        const int c = nt * 8 + 2 * lc;
        *(uint32_t*)(Ob + (size_t)lr * HID + c) =
            pack_h2(of[nt][0] * invl0, of[nt][1] * invl0);
        *(uint32_t*)(Ob + (size_t)(lr + 8) * HID + c) =
            pack_h2(of[nt][2] * invl1, of[nt][3] * invl1);
    }
}

// ===========================================================================
extern "C" void kernel_launch(void* const* d_in, const int* in_sizes, int n_in,
                              void* d_out, int out_size)
{
    const float* X  = (const float*)d_in[0];
    const float* Wq = (const float*)d_in[1];
    const float* bq = (const float*)d_in[2];
    const float* Wk = (const float*)d_in[3];
    const float* bk = (const float*)d_in[4];
    const float* Wv = (const float*)d_in[5];
    const float* bv = (const float*)d_in[6];
    const float* Wo = (const float*)d_in[7];
    const float* bo = (const float*)d_in[8];
    const float* order_gate   = (const float*)d_in[11];
    const float* justice_gate = (const float*)d_in[12];
    float* out = (float*)d_out;

    __half *qp, *kp, *vp, *op, *xh, *w0, *w1, *w2, *w3;
    cudaGetSymbolAddress((void**)&qp, g_Qh);
    cudaGetSymbolAddress((void**)&kp, g_Kh);
    cudaGetSymbolAddress((void**)&vp, g_Vh);
    cudaGetSymbolAddress((void**)&op, g_Oh);
    cudaGetSymbolAddress((void**)&xh, g_Xh);
    cudaGetSymbolAddress((void**)&w0, g_W0h);
    cudaGetSymbolAddress((void**)&w1, g_W1h);
    cudaGetSymbolAddress((void**)&w2, g_W2h);
    cudaGetSymbolAddress((void**)&w3, g_W3h);

    cudaFuncSetAttribute(gemm_qkv,
                         cudaFuncAttributeMaxDynamicSharedMemorySize,
                         GEMM_SMEM_BYTES);
    cudaFuncSetAttribute(gemm_single,
                         cudaFuncAttributeMaxDynamicSharedMemorySize,
                         GEMM_SMEM_BYTES);
    cudaFuncSetAttribute(flash_attn_f16,
                         cudaFuncAttributeMaxDynamicSharedMemorySize,
                         FLASH_SMEM_BYTES);

    const int N4 = (HID * HID) / 4;

    // prepass: convert X, Wq, Wk, Wv to fp16 (Wo rides inside gemm_qkv)
    dim3 rg((N4 + 255) / 256, 4);
    cvt_f16_4<<<rg, 256>>>((const float4*)X,  (const float4*)Wq,
                           (const float4*)Wk, (const float4*)Wv,
                           xh, w0, w1, w2, N4);

    // fused QKV projections + Wo conversion (z = 0/1/2 GEMM, z = 3 cvt)
    dim3 gq(HID / BN, SEQ / BM, 4);   // 8 x 16 x 4
    gemm_qkv<<<gq, 256, GEMM_SMEM_BYTES>>>(xh, w0, w1, w2, bq, bk, bv,
                                           qp, kp, vp,
                                           (const float4*)Wo, w3);

    dim3 ga(SEQ / FAQ, NH);           // 16 x 16
    flash_attn_f16<<<ga, 256, FLASH_SMEM_BYTES>>>(qp, kp, vp, op,
                                                  order_gate, justice_gate);

    dim3 gg(HID / BN, SEQ / BM);      // 8 x 16
    gemm_single<<<gg, 256, GEMM_SMEM_BYTES>>>(op, w3, bo, out);
}

// round 17
// speedup vs baseline: 1.0345x; 1.0009x over previous
#include <cuda_runtime.h>
#include <cuda_fp16.h>
#include <math.h>
#include <stdint.h>

#define SEQ   2048
#define HID   2048
#define HD    128
#define NH    16

// Scratch (device globals: allocation-free rule)
__device__ __half g_Qh[SEQ * HID];
__device__ __half g_Kh[SEQ * HID];
__device__ __half g_Vh[SEQ * HID];
__device__ __half g_Oh[SEQ * HID];
__device__ __half g_Xh[SEQ * HID];
__device__ __half g_W0h[HID * HID];
__device__ __half g_W1h[HID * HID];
__device__ __half g_W2h[HID * HID];
__device__ __half g_W3h[HID * HID];

// ===========================================================================
// Helpers
// ===========================================================================
__device__ __forceinline__ uint32_t smem_u32(const void* p) {
    uint32_t a;
    asm("{ .reg .u64 t; cvta.to.shared.u64 t, %1; cvt.u32.u64 %0, t; }"
        : "=r"(a) : "l"(p));
    return a;
}
__device__ __forceinline__ void cp_async16(uint32_t dst, const void* src) {
    asm volatile("cp.async.cg.shared.global [%0], [%1], 16;" :: "r"(dst), "l"(src));
}
#define CP_COMMIT() asm volatile("cp.async.commit_group;" ::: "memory")
#define CP_WAIT(n)  asm volatile("cp.async.wait_group %0;" :: "n"(n) : "memory")

__device__ __forceinline__ uint32_t pack_h2(float lo, float hi) {
    __half2 h = __floats2half2_rn(lo, hi);   // .x = lo (low 16 bits)
    return *(uint32_t*)&h;
}

// ldmatrix x4 b16 (native)
__device__ __forceinline__ void ldsm_x4(uint32_t r[4], uint32_t addr) {
    asm volatile("ldmatrix.sync.aligned.m8n8.x4.shared.b16 {%0,%1,%2,%3}, [%4];"
        : "=r"(r[0]), "=r"(r[1]), "=r"(r[2]), "=r"(r[3]) : "r"(addr));
}
__device__ __forceinline__ void ldsm_x4_t(uint32_t r[4], uint32_t addr) {
    asm volatile("ldmatrix.sync.aligned.m8n8.x4.trans.shared.b16 {%0,%1,%2,%3}, [%4];"
        : "=r"(r[0]), "=r"(r[1]), "=r"(r[2]), "=r"(r[3]) : "r"(addr));
}

// C[16x8] += A[16x16] * B[8x16]^T   (fp16 in, fp32 accum)
__device__ __forceinline__ void mma_f16(float c[4], const uint32_t a[4],
                                        const uint32_t b[2]) {
    asm volatile(
        "mma.sync.aligned.m16n8k16.row.col.f32.f16.f16.f32 "
        "{%0,%1,%2,%3}, {%4,%5,%6,%7}, {%8,%9}, {%0,%1,%2,%3};"
        : "+f"(c[0]), "+f"(c[1]), "+f"(c[2]), "+f"(c[3])
        : "r"(a[0]), "r"(a[1]), "r"(a[2]), "r"(a[3]), "r"(b[0]), "r"(b[1]));
}

// ===========================================================================
// Fused fp32 -> fp16 conversion prepass (4 tensors: X, Wq, Wk, Wv).
// Wo is converted inside the gemm_qkv launch (z==3 slice) where it overlaps
// the qkv GEMM's partial third wave.
// ===========================================================================
__global__ __launch_bounds__(256) void cvt_f16_4(
    const float4* __restrict__ i0, const float4* __restrict__ i1,
    const float4* __restrict__ i2, const float4* __restrict__ i3,
    __half* __restrict__ o0, __half* __restrict__ o1,
    __half* __restrict__ o2, __half* __restrict__ o3, int n4)
{
    const int z = blockIdx.y;
    const float4* in = (z == 0) ? i0 : (z == 1) ? i1 : (z == 2) ? i2 : i3;
    __half* out      = (z == 0) ? o0 : (z == 1) ? o1 : (z == 2) ? o2 : o3;
    int i = blockIdx.x * blockDim.x + threadIdx.x;
    if (i >= n4) return;
    float4 v = in[i];
    uint2 h;
    h.x = pack_h2(v.x, v.y);
    h.y = pack_h2(v.z, v.w);
    ((uint2*)out)[i] = h;
}

// ===========================================================================
// fp16 mma.sync GEMM core:  C[M,N] = A[M,K] @ B[N,K]^T + bias[N]
// CTA 128x256, 8 warps (2x4) of 64x64, BK=64 halfs, 3-stage cp.async,
// SINGLE __syncthreads per K-chunk (wait -> sync -> issue-next -> compute).
// HALF_OUT: store fp16 (feeds downstream fp16 MMAs); else fp32.
// ===========================================================================
#define BM 128
#define BN 256
#define BK 64
#define NST 3
#define ROWPH 72                            // halfs; 144B rows, conflict-free
#define ATFH (BM * ROWPH)                   // 9216 halfs
#define BTFH (BN * ROWPH)                   // 18432 halfs
#define STFH (ATFH + BTFH)                  // 27648 halfs = 55296 B / stage
#define GEMM_SMEM_BYTES (NST * STFH * 2)    // 165888

__device__ __forceinline__ void gemm_load_stage(
    const __half* __restrict__ Ab, const __half* __restrict__ Bb,
    __half* sm, int slot, int k0, int tid)
{
    const uint32_t sbase = smem_u32(sm) + (uint32_t)(slot * STFH) * 2u;
#pragma unroll
    for (int it = 0; it < 12; it++) {
        const int idx = tid + it * 256;       // 0..3071
        const int r = idx >> 3;               // 0..383
        const int q = idx & 7;                // 8-half (16B) segment
        const __half* src = (r < BM) ? (Ab + (size_t)r * HID + k0 + q * 8)
                                     : (Bb + (size_t)(r - BM) * HID + k0 + q * 8);
        cp_async16(sbase + (uint32_t)(r * ROWPH + q * 8) * 2u, src);
    }
}

template <bool HALF_OUT>
__device__ __forceinline__ void gemm_body(
    const __half* __restrict__ A, const __half* __restrict__ B,
    const float* __restrict__ bias, void* __restrict__ Cv,
    __half* sm, int row0, int col0)
{
    const int tid  = threadIdx.x;
    const int wid  = tid >> 5;
    const int lane = tid & 31;
    const int lr   = lane >> 2;
    const int lc   = lane & 3;
    const int l15  = lane & 15;
    const int klo  = (lane >> 4) << 3;     // 0 or 8 halfs
    const int wm   = (wid >> 2) * 64;
    const int wn   = (wid & 3) * 64;

    const __half* Ab = A + (size_t)row0 * HID;
    const __half* Bb = B + (size_t)col0 * HID;

    float acc[4][8][4];
#pragma unroll
    for (int mt = 0; mt < 4; mt++)
#pragma unroll
        for (int nt = 0; nt < 8; nt++)
#pragma unroll
            for (int i = 0; i < 4; i++) acc[mt][nt][i] = 0.0f;

#pragma unroll
    for (int s = 0; s < NST - 1; s++) {
        gemm_load_stage(Ab, Bb, sm, s, s * BK, tid);
        CP_COMMIT();
    }

    const uint32_t sbase = smem_u32(sm);
    const int KCH = HID / BK;   // 32
    for (int j = 0; j < KCH; j++) {
        CP_WAIT(NST - 2);         // chunk j resident
        __syncthreads();          // all warps done reading slot (j+NST-1)%NST
        if (j + NST - 1 < KCH) {
            gemm_load_stage(Ab, Bb, sm, (j + NST - 1) % NST, (j + NST - 1) * BK, tid);
        }
        CP_COMMIT();              // may be empty near the tail (keeps group math exact)

        const uint32_t sa = sbase + (uint32_t)((j % NST) * STFH) * 2u;
        const uint32_t sb = sa + (uint32_t)ATFH * 2u;

#pragma unroll
        for (int kk = 0; kk < BK; kk += 16) {
            uint32_t af[4][4], bf[8][2];
#pragma unroll
            for (int mt = 0; mt < 4; mt++)
                ldsm_x4(af[mt],
                        sa + (uint32_t)((wm + mt * 16 + l15) * ROWPH + kk + klo) * 2u);
#pragma unroll
            for (int np = 0; np < 4; np++) {
                uint32_t t[4];
                ldsm_x4(t,
                        sb + (uint32_t)((wn + np * 16 + l15) * ROWPH + kk + klo) * 2u);
                bf[2 * np + 0][0] = t[0];
                bf[2 * np + 1][0] = t[1];
                bf[2 * np + 0][1] = t[2];
                bf[2 * np + 1][1] = t[3];
            }
#pragma unroll
            for (int mt = 0; mt < 4; mt++)
#pragma unroll
                for (int nt = 0; nt < 8; nt++)
                    mma_f16(acc[mt][nt], af[mt], bf[nt]);
        }
    }

#pragma unroll
    for (int mt = 0; mt < 4; mt++) {
#pragma unroll
        for (int half = 0; half < 2; half++) {
            const int r = row0 + wm + mt * 16 + lr + half * 8;
#pragma unroll
            for (int nt = 0; nt < 8; nt++) {
                const int c = col0 + wn + nt * 8 + 2 * lc;
                const float vx = acc[mt][nt][half * 2 + 0] + bias[c];
                const float vy = acc[mt][nt][half * 2 + 1] + bias[c + 1];
                if (HALF_OUT) {
                    __half* crow = (__half*)Cv + (size_t)r * HID;
                    *(uint32_t*)(crow + c) = pack_h2(vx, vy);
                } else {
                    float* crow = (float*)Cv + (size_t)r * HID;
                    *(float2*)(crow + c) = make_float2(vx, vy);
                }
            }
        }
    }
}

// Fused QKV projection + Wo conversion: blockIdx.z = 0/1/2 -> GEMM tile;
// blockIdx.z = 3 -> convert one 1/128 chunk of Wo fp32 -> fp16 (these light
// CTAs dispatch last and fill the GEMM's partial third wave).
__global__ __launch_bounds__(256, 1) void gemm_qkv(
    const __half* __restrict__ A,
    const __half* __restrict__ W0, const __half* __restrict__ W1,
    const __half* __restrict__ W2,
    const float* __restrict__ b0, const float* __restrict__ b1,
    const float* __restrict__ b2,
    __half* __restrict__ C0, __half* __restrict__ C1, __half* __restrict__ C2,
    const float4* __restrict__ WoF, __half* __restrict__ WoH)
{
    extern __shared__ __half smh[];
    const int z = blockIdx.z;
    if (z == 3) {
        // convert Wo chunk: 128 CTAs x 8192 float4 (= HID*HID/4 total)
        const int chunk = blockIdx.y * 8 + blockIdx.x;    // 0..127
        const int base  = chunk * 8192;
#pragma unroll
        for (int it = 0; it < 32; it++) {
            const int i = base + it * 256 + threadIdx.x;
            float4 v = WoF[i];
            uint2 h;
            h.x = pack_h2(v.x, v.y);
            h.y = pack_h2(v.z, v.w);
            ((uint2*)WoH)[i] = h;
        }
        return;
    }
    const __half* B   = (z == 0) ? W0 : (z == 1) ? W1 : W2;
    const float* bias = (z == 0) ? b0 : (z == 1) ? b1 : b2;
    __half* C         = (z == 0) ? C0 : (z == 1) ? C1 : C2;
    gemm_body<true>(A, B, bias, C, smh, blockIdx.y * BM, blockIdx.x * BN);
}

// Output projection (fp32 result)
__global__ __launch_bounds__(256, 1) void gemm_single(
    const __half* __restrict__ A, const __half* __restrict__ B,
    const float* __restrict__ bias, float* __restrict__ C)
{
    extern __shared__ __half smh[];
    gemm_body<false>(A, B, bias, C, smh, blockIdx.y * BM, blockIdx.x * BN);
}

// ===========================================================================
// Flash attention, fp16 mma.sync (m16n8k16).
// 1 CTA = 128 q-rows x 1 head, 8 warps, each warp 16 q-rows end-to-end.
// 3-slot KV ring, SINGLE __syncthreads per tile.
// K via ldmatrix.x4 (n-major); V via ldmatrix.x4.trans (k-major).
// ===========================================================================
#define FAQ 128
#define FSK 64
#define FSTG 3
#define KPH 136                       // halfs: 272B rows, conflict-free
#define KTILEH (FSK * KPH)            // 8704 halfs = 17408 B
#define FSTAGEH (2 * KTILEH)          // K + V : 34816 B
#define FLASH_SMEM_BYTES (FSTG * FSTAGEH * 2)   // 104448

__device__ __forceinline__ void flash_load_kv(
    const __half* __restrict__ K, const __half* __restrict__ V,
    __half* sm, int slot, int kt, int hcol, int tid)
{
    const uint32_t ka = smem_u32(sm) + (uint32_t)(slot * FSTAGEH) * 2u;
    const uint32_t va = ka + (uint32_t)KTILEH * 2u;
    const int base = kt * FSK;
#pragma unroll
    for (int it = 0; it < 4; it++) {
        const int idx = tid + it * 256;     // 0..1023
        const int r = idx >> 4;             // 0..63
        const int q = idx & 15;             // 8-half segments
        cp_async16(ka + (uint32_t)(r * KPH + q * 8) * 2u,
                   K + (size_t)(base + r) * HID + hcol + q * 8);
        cp_async16(va + (uint32_t)(r * KPH + q * 8) * 2u,
                   V + (size_t)(base + r) * HID + hcol + q * 8);
    }
}

__global__ __launch_bounds__(256, 1) void flash_attn_f16(
    const __half* __restrict__ Q, const __half* __restrict__ K,
    const __half* __restrict__ V, __half* __restrict__ O,
    const float* __restrict__ order_gate, const float* __restrict__ justice_gate)
{
    extern __shared__ __half fsmh[];

    const int tid  = threadIdx.x;
    const int wid  = tid >> 5;
    const int lane = tid & 31;
    const int lr   = lane >> 2;
    const int lc   = lane & 3;
    const int l15  = lane & 15;
    const int klo  = (lane >> 4) << 3;
    const int hcol = blockIdx.y * HD;
    const int qbase = blockIdx.x * FAQ + wid * 16;

    const float sig_j = 1.0f / (1.0f + __expf(-justice_gate[0]));
    const float sig_o = 1.0f / (1.0f + __expf(-order_gate[0]));
    const float alpha = (1.0f - 0.1f * sig_j) * rsqrtf((float)HD);
    const float obias = sig_o * 0.05f / (float)SEQ;

    // Q fragments (8 k16 chunks), register-resident, loaded straight from gmem
    uint32_t qf[8][4];
    {
        const __half* Qb = Q + (size_t)qbase * HID + hcol;
#pragma unroll
        for (int ks = 0; ks < 8; ks++) {
            qf[ks][0] = *(const uint32_t*)(Qb + (size_t)lr * HID + ks * 16 + 2 * lc);
            qf[ks][1] = *(const uint32_t*)(Qb + (size_t)(lr + 8) * HID + ks * 16 + 2 * lc);
            qf[ks][2] = *(const uint32_t*)(Qb + (size_t)lr * HID + ks * 16 + 2 * lc + 8);
            qf[ks][3] = *(const uint32_t*)(Qb + (size_t)(lr + 8) * HID + ks * 16 + 2 * lc + 8);
        }
    }

    float m0 = -1.0e30f, m1 = -1.0e30f, l0 = 0.0f, l1 = 0.0f;
    float of[16][4];
#pragma unroll
    for (int nt = 0; nt < 16; nt++)
#pragma unroll
        for (int i = 0; i < 4; i++) of[nt][i] = 0.0f;

    flash_load_kv(K, V, fsmh, 0, 0, hcol, tid);
    CP_COMMIT();
    flash_load_kv(K, V, fsmh, 1, 1, hcol, tid);
    CP_COMMIT();

    const int NT = SEQ / FSK;   // 32
    for (int kt = 0; kt < NT; kt++) {
        CP_WAIT(1);             // tile kt resident
        __syncthreads();        // all warps done reading slot (kt+2)%FSTG
        if (kt + 2 < NT) {
            flash_load_kv(K, V, fsmh, (kt + 2) % FSTG, kt + 2, hcol, tid);
        }
        CP_COMMIT();            // may be empty near the tail

        const uint32_t ksa = smem_u32(fsmh) + (uint32_t)((kt % FSTG) * FSTAGEH) * 2u;
        const uint32_t vsa = ksa + (uint32_t)KTILEH * 2u;

        // S = Q K^T : 8 k16 steps over d=128
        float sf[8][4];
#pragma unroll
        for (int nt = 0; nt < 8; nt++)
#pragma unroll
            for (int i = 0; i < 4; i++) sf[nt][i] = 0.0f;

#pragma unroll
        for (int ks = 0; ks < 8; ks++) {
            uint32_t bf[8][2];
#pragma unroll
            for (int np = 0; np < 4; np++) {
                uint32_t t[4];
                ldsm_x4(t, ksa + (uint32_t)((np * 16 + l15) * KPH + ks * 16 + klo) * 2u);
                bf[2 * np + 0][0] = t[0];
                bf[2 * np + 1][0] = t[1];
                bf[2 * np + 0][1] = t[2];
                bf[2 * np + 1][1] = t[3];
            }
#pragma unroll
            for (int nt = 0; nt < 8; nt++)
                mma_f16(sf[nt], qf[ks], bf[nt]);
        }

        // scale + key position bias; row max
        float rmax0 = -1.0e30f, rmax1 = -1.0e30f;
#pragma unroll
        for (int nt = 0; nt < 8; nt++) {
            const float col0 = (float)(kt * FSK + nt * 8 + 2 * lc);
            sf[nt][0] = fmaf(sf[nt][0], alpha, obias * col0);
            sf[nt][1] = fmaf(sf[nt][1], alpha, obias * (col0 + 1.0f));
            sf[nt][2] = fmaf(sf[nt][2], alpha, obias * col0);
            sf[nt][3] = fmaf(sf[nt][3], alpha, obias * (col0 + 1.0f));
            rmax0 = fmaxf(rmax0, fmaxf(sf[nt][0], sf[nt][1]));
            rmax1 = fmaxf(rmax1, fmaxf(sf[nt][2], sf[nt][3]));
        }
#pragma unroll
        for (int off = 1; off < 4; off <<= 1) {
            rmax0 = fmaxf(rmax0, __shfl_xor_sync(0xffffffffu, rmax0, off));
            rmax1 = fmaxf(rmax1, __shfl_xor_sync(0xffffffffu, rmax1, off));
        }
        const float m0n = fmaxf(m0, rmax0);
        const float m1n = fmaxf(m1, rmax1);
        const float corr0 = __expf(m0 - m0n);
        const float corr1 = __expf(m1 - m1n);

        // exp + row sums + fp16 P fragments (in-thread pack, no shuffles)
        float rsum0 = 0.0f, rsum1 = 0.0f;
        uint32_t ph[8][2];
#pragma unroll
        for (int nt = 0; nt < 8; nt++) {
            const float e0 = __expf(sf[nt][0] - m0n);
            const float e1 = __expf(sf[nt][1] - m0n);
            const float e2 = __expf(sf[nt][2] - m1n);
            const float e3 = __expf(sf[nt][3] - m1n);
            rsum0 += e0 + e1;
            rsum1 += e2 + e3;
            ph[nt][0] = pack_h2(e0, e1);   // row lr,   keys {nt*8+2lc, +1}
            ph[nt][1] = pack_h2(e2, e3);   // row lr+8, same keys
        }
#pragma unroll
        for (int off = 1; off < 4; off <<= 1) {
            rsum0 += __shfl_xor_sync(0xffffffffu, rsum0, off);
            rsum1 += __shfl_xor_sync(0xffffffffu, rsum1, off);
        }
        l0 = l0 * corr0 + rsum0; m0 = m0n;
        l1 = l1 * corr1 + rsum1; m1 = m1n;

#pragma unroll
        for (int nt = 0; nt < 16; nt++) {
            of[nt][0] *= corr0; of[nt][1] *= corr0;
            of[nt][2] *= corr1; of[nt][3] *= corr1;
        }

        // O += P V : 4 k16 chunks over 64 keys; V via ldmatrix.trans
#pragma unroll
        for (int kp = 0; kp < 4; kp++) {
            uint32_t pa[4];
            pa[0] = ph[2 * kp + 0][0];
            pa[1] = ph[2 * kp + 0][1];
            pa[2] = ph[2 * kp + 1][0];
            pa[3] = ph[2 * kp + 1][1];
#pragma unroll
            for (int dg = 0; dg < 8; dg++) {
                uint32_t t[4];
                ldsm_x4_t(t, vsa + (uint32_t)((kp * 16 + l15) * KPH + dg * 16 + klo) * 2u);
                uint32_t b0[2] = {t[0], t[1]};
                uint32_t b1[2] = {t[2], t[3]};
                mma_f16(of[2 * dg + 0], pa, b0);
                mma_f16(of[2 * dg + 1], pa, b1);
            }
        }
    }

    // normalize + fp16 write (feeds final fp16 GEMM)
    const float invl0 = 1.0f / l0;
    const float invl1 = 1.0f / l1;
    __half* Ob = O + (size_t)qbase * HID + hcol;
#pragma unroll
    for (int nt = 0; nt < 16; nt++) {
        const int c = nt * 8 + 2 * lc;
        *(uint32_t*)(Ob + (size_t)lr * HID + c) =
            pack_h2(of[nt][0] * invl0, of[nt][1] * invl0);
        *(uint32_t*)(Ob + (size_t)(lr + 8) * HID + c) =
            pack_h2(of[nt][2] * invl1, of[nt][3] * invl1);
    }
}

// ===========================================================================
extern "C" void kernel_launch(void* const* d_in, const int* in_sizes, int n_in,
                              void* d_out, int out_size)
{
    const float* X  = (const float*)d_in[0];
    const float* Wq = (const float*)d_in[1];
    const float* bq = (const float*)d_in[2];
    const float* Wk = (const float*)d_in[3];
    const float* bk = (const float*)d_in[4];
    const float* Wv = (const float*)d_in[5];
    const float* bv = (const float*)d_in[6];
    const float* Wo = (const float*)d_in[7];
    const float* bo = (const float*)d_in[8];
    const float* order_gate   = (const float*)d_in[11];
    const float* justice_gate = (const float*)d_in[12];
    float* out = (float*)d_out;

    __half *qp, *kp, *vp, *op, *xh, *w0, *w1, *w2, *w3;
    cudaGetSymbolAddress((void**)&qp, g_Qh);
    cudaGetSymbolAddress((void**)&kp, g_Kh);
    cudaGetSymbolAddress((void**)&vp, g_Vh);
    cudaGetSymbolAddress((void**)&op, g_Oh);
    cudaGetSymbolAddress((void**)&xh, g_Xh);
    cudaGetSymbolAddress((void**)&w0, g_W0h);
    cudaGetSymbolAddress((void**)&w1, g_W1h);
    cudaGetSymbolAddress((void**)&w2, g_W2h);
    cudaGetSymbolAddress((void**)&w3, g_W3h);

    cudaFuncSetAttribute(gemm_qkv,
                         cudaFuncAttributeMaxDynamicSharedMemorySize,
                         GEMM_SMEM_BYTES);
    cudaFuncSetAttribute(gemm_single,
                         cudaFuncAttributeMaxDynamicSharedMemorySize,
                         GEMM_SMEM_BYTES);
    cudaFuncSetAttribute(flash_attn_f16,
                         cudaFuncAttributeMaxDynamicSharedMemorySize,
                         FLASH_SMEM_BYTES);

    const int N4 = (HID * HID) / 4;

    // prepass: convert X, Wq, Wk, Wv to fp16 (Wo rides inside gemm_qkv)
    dim3 rg((N4 + 255) / 256, 4);
    cvt_f16_4<<<rg, 256>>>((const float4*)X,  (const float4*)Wq,
                           (const float4*)Wk, (const float4*)Wv,
                           xh, w0, w1, w2, N4);

    // fused QKV projections + Wo conversion (z = 0/1/2 GEMM, z = 3 cvt)
    dim3 gq(HID / BN, SEQ / BM, 4);   // 8 x 16 x 4
    gemm_qkv<<<gq, 256, GEMM_SMEM_BYTES>>>(xh, w0, w1, w2, bq, bk, bv,
                                           qp, kp, vp,
                                           (const float4*)Wo, w3);

    dim3 ga(SEQ / FAQ, NH);           // 16 x 16
    flash_attn_f16<<<ga, 256, FLASH_SMEM_BYTES>>>(qp, kp, vp, op,
                                                  order_gate, justice_gate);

    dim3 gg(HID / BN, SEQ / BM);      // 8 x 16
    gemm_single<<<gg, 256, GEMM_SMEM_BYTES>>>(op, w3, bo, out);
}